// round 4
// baseline (speedup 1.0000x reference)
#include <cuda_runtime.h>
#include <cuda_pipeline_primitives.h>

// Problem constants (fixed by the reference):
//   image 1000x1000, patch 5x5 -> 200x200 = 40000 patches
//   coefficients [40000, 3, 10, 2], bias [40000, 3]
//   out [3, 1000000]
#define IMG_W           1000
#define NUM_PIX         1000000
#define PATCH           5
#define PATCHES_PER_ROW 200
#define COEF_PER_PATCH  60          // 3*10*2
#define PB              40          // patches per block (one fifth of a patch-row)
#define NTHREADS        256         // 200 compute threads + spare for copies
#define SM_STRIDE       68          // 60 padded to 68 floats: conflict-free LDS.128

__global__ __launch_bounds__(NTHREADS, 6)
void ts_kernel(const float* __restrict__ pix,
               const float* __restrict__ coef,
               const float* __restrict__ bias,
               float* __restrict__ out)
{
    __shared__ float sc[PB * SM_STRIDE];            // 40*68*4   = 10880 B
    __shared__ float sb[PB * 3 + 4];                //            ~496 B (cp.async 16B granules)
    __shared__ float sp[PATCH * 2 * (PB * PATCH)];  // 5*400*4   =  8000 B (pixels)
    __shared__ float so[3 * PATCH * (PB * PATCH)];  // 3*5*200*4 = 12000 B (output)

    const int tid = threadIdx.x;
    const int b   = blockIdx.x;          // 0..999
    const int pr  = b / 5;               // patch row 0..199
    const int cb  = (b - pr * 5) * PB;   // patch-col base: 0,40,80,120,160
    const int pbase = pr * PATCHES_PER_ROW + cb;
    const int colBase = cb * PATCH;      // pixel column base (multiple of 200)

    // ---- Phase 1: cp.async (LDGSTS) cooperative loads, all 16B, coalesced ----
    {
        // Coefficients: 600 float4, contiguous in gmem -> padded rows in smem.
        const float4* g4 = (const float4*)(coef + (size_t)pbase * COEF_PER_PATCH);
        #pragma unroll
        for (int k = 0; k < 3; k++) {
            int idx = tid + k * NTHREADS;
            if (idx < 600) {
                int pp  = idx / 15;        // 15 float4 per patch
                int off = idx - pp * 15;
                __pipeline_memcpy_async(&sc[pp * SM_STRIDE + off * 4], &g4[idx], 16);
            }
        }
        // Bias: 120 floats = 30 float4 (pbase*3 floats is 480B-aligned).
        if (tid < 30)
            __pipeline_memcpy_async(&sb[tid * 4],
                                    (const float4*)(bias + (size_t)pbase * 3) + tid, 16);
        // Pixels: 5 image rows x 200 px x 2 floats = 500 float4, rows contiguous.
        const float4* p4 = (const float4*)pix;
        const int rowf4base = (pr * PATCH * IMG_W + colBase) >> 1;  // float4 index of row 0
        #pragma unroll
        for (int k = 0; k < 2; k++) {
            int idx = tid + k * NTHREADS;
            if (idx < 500) {
                int r   = idx / 100;       // image row within strip (0..4)
                int off = idx - r * 100;   // float4 within row
                __pipeline_memcpy_async(&sp[r * 400 + off * 4],
                                        &p4[rowf4base + r * (IMG_W / 2) + off], 16);
            }
        }
        __pipeline_commit();
        __pipeline_wait_prior(0);
    }
    __syncthreads();

    // ---- Phase 2: compute (200 threads; thread = 5-pixel segment of one patch) ----
    if (tid < PB * PATCH) {
        const int p_local = tid % PB;        // 0..39
        const int seg     = tid / PB;        // 0..4 (pixel row within patch)

        // Pixel coords from smem: 5 LDS.64, conflict-free (40B lane stride)
        float x[PATCH], y[PATCH];
        {
            const float* ps = &sp[seg * 400 + p_local * 10];
            #pragma unroll
            for (int i = 0; i < PATCH; i++) {
                float2 v = *(const float2*)&ps[2 * i];
                x[i] = v.x; y[i] = v.y;
            }
        }

        const float* cc0 = &sc[p_local * SM_STRIDE];

        #pragma unroll
        for (int ch = 0; ch < 3; ch++) {
            const float* cc = cc0 + ch * 20;   // [t*2+d], t=0..9, d in {x,y}
            const float bv = sb[p_local * 3 + ch];

            float rx[PATCH], ry[PATCH];
            {
                float4 v = *(const float4*)(cc + 16);   // (cx8, cy8, cx9, cy9)
                #pragma unroll
                for (int i = 0; i < PATCH; i++) {
                    rx[i] = fmaf(v.z, x[i], v.x);
                    ry[i] = fmaf(v.w, y[i], v.y);
                }
            }
            #pragma unroll
            for (int j = 3; j >= 0; j--) {
                float4 v = *(const float4*)(cc + j * 4);  // (cx_2j, cy_2j, cx_2j+1, cy_2j+1)
                #pragma unroll
                for (int i = 0; i < PATCH; i++) {
                    rx[i] = fmaf(rx[i], x[i], v.z);
                    ry[i] = fmaf(ry[i], y[i], v.w);
                }
                #pragma unroll
                for (int i = 0; i < PATCH; i++) {
                    rx[i] = fmaf(rx[i], x[i], v.x);
                    ry[i] = fmaf(ry[i], y[i], v.y);
                }
            }
            float* dst = &so[(ch * PATCH + seg) * (PB * PATCH) + p_local * PATCH];
            #pragma unroll
            for (int i = 0; i < PATCH; i++)
                dst[i] = rx[i] + ry[i] + bv;
        }
    }
    __syncthreads();

    // ---- Phase 3: coalesced float4 output copy ----
    {
        const float4* s4 = (const float4*)so;
        #pragma unroll
        for (int k = 0; k < 3; k++) {
            int j = tid + k * NTHREADS;
            if (j < 750) {
                int chseg = j / 50;           // 50 float4 per (ch,seg) row
                int off   = j - chseg * 50;
                int ch    = chseg / PATCH;
                int seg   = chseg - ch * PATCH;
                int gfl   = ch * NUM_PIX + (pr * PATCH + seg) * IMG_W + colBase + off * 4;
                *(float4*)&out[gfl] = s4[j];
            }
        }
    }
}

extern "C" void kernel_launch(void* const* d_in, const int* in_sizes, int n_in,
                              void* d_out, int out_size)
{
    const float* pix  = (const float*)d_in[0];   // [1000000, 2]
    const float* coef = (const float*)d_in[1];   // [40000, 3, 10, 2]
    const float* bias = (const float*)d_in[2];   // [40000, 3]
    float* out = (float*)d_out;                  // [3, 1000000]

    (void)in_sizes; (void)n_in; (void)out_size;
    ts_kernel<<<1000, NTHREADS>>>(pix, coef, bias, out);
}

// round 5
// speedup vs baseline: 1.0781x; 1.0781x over previous
#include <cuda_runtime.h>
#include <cuda_pipeline_primitives.h>

// Problem constants (fixed by the reference):
//   image 1000x1000, patch 5x5 -> 200x200 = 40000 patches
//   coefficients [40000, 3, 10, 2], bias [40000, 3]
//   out [3, 1000000]
#define IMG_W           1000
#define NUM_PIX         1000000
#define PATCH           5
#define PATCHES_PER_ROW 200
#define COEF_PER_PATCH  60          // 3*10*2
#define PB              40          // patches per block (one fifth of a patch-row)
#define NTHREADS        256         // 200 compute threads + spare for copies
#define SM_STRIDE       68          // 60 padded to 68 floats: 16B-aligned rows, conflict-free LDS.128

// Packed dual-FP32 FMA (Blackwell): {d.lo,d.hi} = {a.lo*b.lo+c.lo, a.hi*b.hi+c.hi}
__device__ __forceinline__ unsigned long long ffma2(unsigned long long a,
                                                    unsigned long long b,
                                                    unsigned long long c)
{
    unsigned long long d;
    asm("fma.rn.f32x2 %0, %1, %2, %3;" : "=l"(d) : "l"(a), "l"(b), "l"(c));
    return d;
}
__device__ __forceinline__ unsigned long long as_u64(double v)
{
    return __double_as_longlong(v);
}
__device__ __forceinline__ float hsum2(unsigned long long v)
{
    float lo, hi;
    asm("mov.b64 {%0, %1}, %2;" : "=f"(lo), "=f"(hi) : "l"(v));
    return lo + hi;
}

__global__ __launch_bounds__(NTHREADS, 6)
void ts_kernel(const float* __restrict__ pix,
               const float* __restrict__ coef,
               const float* __restrict__ bias,
               float* __restrict__ out)
{
    __shared__ float sc[PB * SM_STRIDE];            // 40*68*4   = 10880 B
    __shared__ float sb[PB * 3 + 4];                //            ~496 B (cp.async 16B granules)
    __shared__ float sp[PATCH * 2 * (PB * PATCH)];  // 5*400*4   =  8000 B (pixels)
    __shared__ float so[3 * PATCH * (PB * PATCH)];  // 3*5*200*4 = 12000 B (output)

    const int tid = threadIdx.x;
    const int b   = blockIdx.x;          // 0..999
    const int pr  = b / 5;               // patch row 0..199
    const int cb  = (b - pr * 5) * PB;   // patch-col base: 0,40,80,120,160
    const int pbase = pr * PATCHES_PER_ROW + cb;
    const int colBase = cb * PATCH;      // pixel column base (multiple of 200)

    // ---- Phase 1: cp.async (LDGSTS) cooperative loads, all 16B, coalesced ----
    {
        const float4* g4 = (const float4*)(coef + (size_t)pbase * COEF_PER_PATCH);
        #pragma unroll
        for (int k = 0; k < 3; k++) {
            int idx = tid + k * NTHREADS;
            if (idx < 600) {
                int pp  = idx / 15;        // 15 float4 per patch
                int off = idx - pp * 15;
                __pipeline_memcpy_async(&sc[pp * SM_STRIDE + off * 4], &g4[idx], 16);
            }
        }
        if (tid < 30)
            __pipeline_memcpy_async(&sb[tid * 4],
                                    (const float4*)(bias + (size_t)pbase * 3) + tid, 16);
        const float4* p4 = (const float4*)pix;
        const int rowf4base = (pr * PATCH * IMG_W + colBase) >> 1;
        #pragma unroll
        for (int k = 0; k < 2; k++) {
            int idx = tid + k * NTHREADS;
            if (idx < 500) {
                int r   = idx / 100;       // image row within strip (0..4)
                int off = idx - r * 100;   // float4 within row
                __pipeline_memcpy_async(&sp[r * 400 + off * 4],
                                        &p4[rowf4base + r * (IMG_W / 2) + off], 16);
            }
        }
        __pipeline_commit();
        __pipeline_wait_prior(0);
    }
    __syncthreads();

    // ---- Phase 2: compute with packed f32x2 FMA ----
    // Thread = 5-pixel row segment of one patch. Accumulator {rx,ry} per pixel,
    // coefficient pairs (cx_t, cy_t) are adjacent in memory = one packed operand.
    if (tid < PB * PATCH) {
        const int p_local = tid % PB;        // 0..39
        const int seg     = tid / PB;        // 0..4 (pixel row within patch)

        // Packed (x,y) per pixel: 5 LDS.64, conflict-free (40B lane stride)
        unsigned long long xy[PATCH];
        {
            const double* ps = (const double*)&sp[seg * 400 + p_local * 10];
            #pragma unroll
            for (int i = 0; i < PATCH; i++)
                xy[i] = as_u64(ps[i]);
        }

        const float* cc0 = &sc[p_local * SM_STRIDE];

        #pragma unroll
        for (int ch = 0; ch < 3; ch++) {
            // cp[j] = pairs (t=2j, t=2j+1); 16B-aligned (272,80,16 all multiples of 16)
            const double2* cp = (const double2*)(cc0 + ch * 20);
            const float bv = sb[p_local * 3 + ch];

            unsigned long long acc[PATCH];
            {
                double2 v = cp[4];                       // pairs t=8, t=9
                const unsigned long long c8 = as_u64(v.x), c9 = as_u64(v.y);
                #pragma unroll
                for (int i = 0; i < PATCH; i++)
                    acc[i] = ffma2(c9, xy[i], c8);       // t=9 -> t=8
            }
            #pragma unroll
            for (int j = 3; j >= 0; j--) {
                double2 v = cp[j];                       // pairs t=2j, t=2j+1
                const unsigned long long clo = as_u64(v.x), chi = as_u64(v.y);
                #pragma unroll
                for (int i = 0; i < PATCH; i++)
                    acc[i] = ffma2(acc[i], xy[i], chi);  // t = 2j+1
                #pragma unroll
                for (int i = 0; i < PATCH; i++)
                    acc[i] = ffma2(acc[i], xy[i], clo);  // t = 2j
            }
            float* dst = &so[(ch * PATCH + seg) * (PB * PATCH) + p_local * PATCH];
            #pragma unroll
            for (int i = 0; i < PATCH; i++)
                dst[i] = hsum2(acc[i]) + bv;             // rx + ry + bias
        }
    }
    __syncthreads();

    // ---- Phase 3: coalesced float4 output copy ----
    {
        const float4* s4 = (const float4*)so;
        #pragma unroll
        for (int k = 0; k < 3; k++) {
            int j = tid + k * NTHREADS;
            if (j < 750) {
                int chseg = j / 50;           // 50 float4 per (ch,seg) row
                int off   = j - chseg * 50;
                int ch    = chseg / PATCH;
                int seg   = chseg - ch * PATCH;
                int gfl   = ch * NUM_PIX + (pr * PATCH + seg) * IMG_W + colBase + off * 4;
                *(float4*)&out[gfl] = s4[j];
            }
        }
    }
}

extern "C" void kernel_launch(void* const* d_in, const int* in_sizes, int n_in,
                              void* d_out, int out_size)
{
    const float* pix  = (const float*)d_in[0];   // [1000000, 2]
    const float* coef = (const float*)d_in[1];   // [40000, 3, 10, 2]
    const float* bias = (const float*)d_in[2];   // [40000, 3]
    float* out = (float*)d_out;                  // [3, 1000000]

    (void)in_sizes; (void)n_in; (void)out_size;
    ts_kernel<<<1000, NTHREADS>>>(pix, coef, bias, out);
}